// round 15
// baseline (speedup 1.0000x reference)
#include <cuda_runtime.h>
#include <cuda_fp16.h>

// CapLayer fused capsule routing. 296 CTAs x 512 threads, 2 CTAs/SM,
// 2 batch elems/CTA. fp16 data streams (x in smem padded rows, W/WT global
// halves), fp32 accumulation. Phase B uses per-lane j-ownership: full-row
// dots, ZERO shuffles. Telescoped routing logits (no Phase E).
// x:    d_in[0]  float [512][256][6][6]   (channel = g*8+k, g<32, k<8)
// W:    d_in[2]  float [5120][8] ; flat = g*1280 + p*8 + k   (p = j*16+d)
// bias: d_in[3]  float [5120]    ; flat = g*160  + j*16 + d
// out:  float [512][10][16]

#define LOG2E 1.4426950408889634f

__device__ __half g_hW[40960];    // [g][p][k]
__device__ __half g_hWT[40960];   // [g][j][k][d]  (d contiguous)

struct Smem {
    __half xh[2][256 * 40];  // 40960 B, [e][gk][hw] rows padded to 40 halves
    float cbuf[16][400];     // 25600 B, per-warp c [w][j*40+hw] (rows padded)
    float scr[16][192];      // per-warp, per-elem 96: [0..79] vW[j][k], [80..89] vb[j]
    float cx[2][2560];       // [e][j][g][k]
    float csum[2][320];      // [e][j][g]
    float sWsB[2][320];      // sW=[0..159], sB=[160..319]; xsum aliases [0..255]
    float vsum[2][160];      // LOG2E * accumulated v
};                           // 105728 B (2 CTAs/SM: 211456 <= 227KB)

__device__ __forceinline__ float ex2_approx(float x) {
    float y; asm("ex2.approx.ftz.f32 %0, %1;" : "=f"(y) : "f"(x)); return y;
}
__device__ __forceinline__ float rcp_approx(float x) {
    float y; asm("rcp.approx.ftz.f32 %0, %1;" : "=f"(y) : "f"(x)); return y;
}
__device__ __forceinline__ float dot4(float4 a, float4 b) {
    return a.x * b.x + a.y * b.y + a.z * b.z + a.w * b.w;
}
__device__ __forceinline__ float sum4(float4 a) {
    return a.x + a.y + a.z + a.w;
}
__device__ __forceinline__ void h8_to_f(uint4 h, float4& lo, float4& hi) {
    const __half2* hp = reinterpret_cast<const __half2*>(&h);
    float2 f0 = __half22float2(hp[0]);
    float2 f1 = __half22float2(hp[1]);
    float2 f2 = __half22float2(hp[2]);
    float2 f3 = __half22float2(hp[3]);
    lo = make_float4(f0.x, f0.y, f1.x, f1.y);
    hi = make_float4(f2.x, f2.y, f3.x, f3.y);
}
__device__ __forceinline__ float4 h4_to_f(uint2 u) {
    const __half2* hp = reinterpret_cast<const __half2*>(&u);
    float2 f0 = __half22float2(hp[0]);
    float2 f1 = __half22float2(hp[1]);
    return make_float4(f0.x, f0.y, f1.x, f1.y);
}

__global__ void prep_W_kernel(const float* __restrict__ W) {
    int i = blockIdx.x * 256 + threadIdx.x;
    if (i < 40960) {
        float v = W[i];                 // i = g*1280 + j*128 + d*8 + k
        g_hW[i] = __float2half(v);
        int k = i & 7, d = (i >> 3) & 15;
        int gj128 = i & ~127;           // block base (128 floats per (g,j))
        g_hWT[gj128 + k * 16 + d] = __float2half(v);
    }
}

__global__ __launch_bounds__(512, 2)
void caps_kernel(const float* __restrict__ x_g,
                 const float* __restrict__ W,
                 const float* __restrict__ bias,
                 float* __restrict__ out) {
    extern __shared__ float smem_raw[];
    Smem* S = reinterpret_cast<Smem*>(smem_raw);

    const int cta  = blockIdx.x;
    const bool two = (cta < 216);
    const int b0   = two ? cta * 2 : 432 + (cta - 216);
    const int b1   = two ? b0 + 1 : b0;
    const int tid  = threadIdx.x;
    const int w    = tid >> 5;
    const int lane = tid & 31;

    const float* x0g = x_g + (size_t)b0 * 9216;
    const float* x1g = x_g + (size_t)b1 * 9216;

    // ---- load x (coalesced float4), convert fp16, store padded rows ----
    for (int i = tid; i < 2304; i += 512) {
        int row  = i / 9;             // 36 floats per row = 9 float4s
        int col  = (i - row * 9) * 4; // 0,4,...,32
        int dsth = row * 40 + col;    // halves; byte off 2*dsth is 8B aligned
        float4 v0 = reinterpret_cast<const float4*>(x0g)[i];
        float4 v1 = reinterpret_cast<const float4*>(x1g)[i];
        __half2 a0 = __floats2half2_rn(v0.x, v0.y);
        __half2 c0 = __floats2half2_rn(v0.z, v0.w);
        __half2 a1 = __floats2half2_rn(v1.x, v1.y);
        __half2 c1 = __floats2half2_rn(v1.z, v1.w);
        uint2 u0, u1;
        u0.x = *reinterpret_cast<unsigned*>(&a0);
        u0.y = *reinterpret_cast<unsigned*>(&c0);
        u1.x = *reinterpret_cast<unsigned*>(&a1);
        u1.y = *reinterpret_cast<unsigned*>(&c1);
        *reinterpret_cast<uint2*>(&S->xh[0][dsth]) = u0;
        *reinterpret_cast<uint2*>(&S->xh[1][dsth]) = u1;
    }
    __syncthreads();

    // ---- xsum[e][g][k] = sum_hw x ----
    {
        const int e = tid >> 8, idx = tid & 255;
        const __half2* p = reinterpret_cast<const __half2*>(S->xh[e] + idx * 40);
        float acc = 0.f;
        #pragma unroll
        for (int t = 0; t < 18; t++) {
            float2 f = __half22float2(p[t]);
            acc += f.x + f.y;
        }
        S->sWsB[e][idx] = acc;
    }
    __syncthreads();

    // iter 1 shortcut: c uniform 0.1 -> cx = 0.1*xsum (all j)
    for (int i = tid; i < 5120; i += 512) {
        const int e = (i >= 2560);
        const int ii = i - e * 2560;
        S->cx[0][i] = 0.1f * S->sWsB[e][ii & 255];
    }
    __syncthreads();

    for (int it = 0; it < 3; ++it) {
        if (it > 0) {
            #pragma unroll
            for (int gi = 0; gi < 2; gi++) {
                const int g = w + gi * 16;
                float* scr = S->scr[w];

                // --- A-pre: fp16 WT, shared loads for both elements ---
                {
                    const __half* hWT = g_hWT + g * 1280;
                    const float4* vs0 = reinterpret_cast<const float4*>(S->vsum[0]);
                    const float4* vs1 = reinterpret_cast<const float4*>(S->vsum[1]);
                    const int jj = lane >> 4;
                    const int kk = (lane & 15) >> 1;
                    const int dh = lane & 1;
                    #pragma unroll
                    for (int r = 0; r < 5; r++) {
                        const int j = 2 * r + jj;
                        uint4 h = *reinterpret_cast<const uint4*>(
                            hWT + j * 128 + kk * 16 + dh * 8);
                        float4 lo, hi;
                        h8_to_f(h, lo, hi);
                        float4 va0 = vs0[j * 4 + dh * 2], vb0 = vs0[j * 4 + dh * 2 + 1];
                        float4 va1 = vs1[j * 4 + dh * 2], vb1 = vs1[j * 4 + dh * 2 + 1];
                        float p0 = dot4(lo, va0) + dot4(hi, vb0);
                        float p1 = dot4(lo, va1) + dot4(hi, vb1);
                        p0 += __shfl_xor_sync(0xffffffffu, p0, 1);
                        p1 += __shfl_xor_sync(0xffffffffu, p1, 1);
                        if (dh == 0) {
                            scr[j * 8 + kk]      = p0;
                            scr[96 + j * 8 + kk] = p1;
                        }
                    }
                    const float4* Bv = reinterpret_cast<const float4*>(bias);
                    float4 fa = Bv[g * 40 + lane];
                    float4 fb = Bv[g * 40 + 32 + (lane & 7)];
                    float pa0 = dot4(fa, vs0[lane]);
                    float pa1 = dot4(fa, vs1[lane]);
                    float pb0 = dot4(fb, vs0[32 + (lane & 7)]);
                    float pb1 = dot4(fb, vs1[32 + (lane & 7)]);
                    pa0 += __shfl_xor_sync(0xffffffffu, pa0, 1);
                    pa0 += __shfl_xor_sync(0xffffffffu, pa0, 2);
                    pa1 += __shfl_xor_sync(0xffffffffu, pa1, 1);
                    pa1 += __shfl_xor_sync(0xffffffffu, pa1, 2);
                    pb0 += __shfl_xor_sync(0xffffffffu, pb0, 1);
                    pb0 += __shfl_xor_sync(0xffffffffu, pb0, 2);
                    pb1 += __shfl_xor_sync(0xffffffffu, pb1, 1);
                    pb1 += __shfl_xor_sync(0xffffffffu, pb1, 2);
                    if ((lane & 3) == 0) {
                        scr[80 + (lane >> 2)] = pa0;
                        scr[96 + 80 + (lane >> 2)] = pa1;
                        if (lane < 8) {
                            scr[88 + (lane >> 2)] = pb0;
                            scr[96 + 88 + (lane >> 2)] = pb1;
                        }
                    }
                }
                __syncwarp();

                #pragma unroll
                for (int e = 0; e < 2; e++) {
                    const float* se = scr + e * 96;
                    const __half* xge = S->xh[e];
                    // Phase A: logits -> softmax over j -> c (padded rows)
                    {
                        const __half* xr = xge + g * 320;   // 8 rows * 40
                        float xv[8], xv2[8];
                        #pragma unroll
                        for (int k = 0; k < 8; k++) {
                            xv[k]  = __half2float(xr[k * 40 + lane]);
                            xv2[k] = __half2float(xr[k * 40 + 32 + (lane & 3)]);
                        }
                        float bb[10], bb2[10];
                        #pragma unroll
                        for (int j = 0; j < 10; j++) {
                            const float4* vwp = reinterpret_cast<const float4*>(se + j * 8);
                            float4 w0 = vwp[0], w1 = vwp[1];
                            float t0 = se[80 + j];
                            float a  = t0, a2 = t0;
                            a  += w0.x*xv[0] + w0.y*xv[1] + w0.z*xv[2] + w0.w*xv[3]
                                + w1.x*xv[4] + w1.y*xv[5] + w1.z*xv[6] + w1.w*xv[7];
                            a2 += w0.x*xv2[0] + w0.y*xv2[1] + w0.z*xv2[2] + w0.w*xv2[3]
                                + w1.x*xv2[4] + w1.y*xv2[5] + w1.z*xv2[6] + w1.w*xv2[7];
                            bb[j] = a; bb2[j] = a2;
                        }
                        float Z = 0.f, Z2 = 0.f;
                        #pragma unroll
                        for (int j = 0; j < 10; j++) {
                            bb[j]  = ex2_approx(bb[j]);   Z  += bb[j];
                            bb2[j] = ex2_approx(bb2[j]);  Z2 += bb2[j];
                        }
                        float r  = rcp_approx(Z);
                        float r2 = rcp_approx(Z2);
                        float* cw = S->cbuf[w];
                        #pragma unroll
                        for (int j = 0; j < 10; j++) {
                            cw[j * 40 + lane] = bb[j] * r;
                            if (lane < 4) cw[j * 40 + 32 + lane] = bb2[j] * r2;
                        }
                    }
                    __syncwarp();
                    // Phase B: per-lane j-ownership, full-row dots, no shuffles
                    {
                        const int k = lane >> 2, q = lane & 3;
                        const int j0 = (q == 0) ? 0 : (q == 1) ? 3 : (q == 2) ? 6 : 8;
                        const int jn = (q < 2) ? 3 : 2;
                        const __half* xr = xge + (g * 8 + k) * 40;
                        uint4 xa = *reinterpret_cast<const uint4*>(xr);
                        uint4 xb = *reinterpret_cast<const uint4*>(xr + 8);
                        uint4 xc = *reinterpret_cast<const uint4*>(xr + 16);
                        uint4 xd = *reinterpret_cast<const uint4*>(xr + 24);
                        uint2 xe2 = *reinterpret_cast<const uint2*>(xr + 32);
                        uint2 chunks[9] = {
                            {xa.x, xa.y}, {xa.z, xa.w},
                            {xb.x, xb.y}, {xb.z, xb.w},
                            {xc.x, xc.y}, {xc.z, xc.w},
                            {xd.x, xd.y}, {xd.z, xd.w},
                            xe2
                        };
                        const float* cb = S->cbuf[w] + j0 * 40;
                        float acc0 = 0.f, acc1 = 0.f, acc2 = 0.f;
                        float cs0 = 0.f, cs1 = 0.f, cs2 = 0.f;
                        #pragma unroll
                        for (int t = 0; t < 9; t++) {
                            float4 xt = h4_to_f(chunks[t]);
                            float4 c0 = reinterpret_cast<const float4*>(cb)[t];
                            float4 c1 = reinterpret_cast<const float4*>(cb + 40)[t];
                            acc0 += dot4(c0, xt);  cs0 += sum4(c0);
                            acc1 += dot4(c1, xt);  cs1 += sum4(c1);
                            if (jn == 3) {
                                float4 c2 = reinterpret_cast<const float4*>(cb + 80)[t];
                                acc2 += dot4(c2, xt);  cs2 += sum4(c2);
                            }
                        }
                        S->cx[e][(j0 + 0) * 256 + g * 8 + k] = acc0;
                        S->cx[e][(j0 + 1) * 256 + g * 8 + k] = acc1;
                        if (jn == 3) S->cx[e][(j0 + 2) * 256 + g * 8 + k] = acc2;
                        if (k == 0) {
                            S->csum[e][(j0 + 0) * 32 + g] = cs0;
                            S->csum[e][(j0 + 1) * 32 + g] = cs1;
                            if (jn == 3) S->csum[e][(j0 + 2) * 32 + g] = cs2;
                        }
                    }
                    __syncwarp();
                }
            }
            __syncthreads();
        }

        // ===== Phase C: fp16 W, one 16B load = all 8 k; both elements =====
        if (tid < 320) {
            const int p  = tid >> 1;
            const int gh = tid & 1;
            const int j  = p >> 4;
            const float4* cxv0 = reinterpret_cast<const float4*>(S->cx[0]);
            const float4* cxv1 = reinterpret_cast<const float4*>(S->cx[1]);
            float acc0 = 0.f, acc1 = 0.f;
            #pragma unroll 8
            for (int gg = 0; gg < 16; gg++) {
                const int g = gg * 2 + gh;
                uint4 h = *reinterpret_cast<const uint4*>(&g_hW[g * 1280 + p * 8]);
                float4 lo, hi;
                h8_to_f(h, lo, hi);
                acc0 += dot4(lo, cxv0[j * 64 + g * 2]) + dot4(hi, cxv0[j * 64 + g * 2 + 1]);
                acc1 += dot4(lo, cxv1[j * 64 + g * 2]) + dot4(hi, cxv1[j * 64 + g * 2 + 1]);
            }
            acc0 += __shfl_xor_sync(0xffffffffu, acc0, 1);
            acc1 += __shfl_xor_sync(0xffffffffu, acc1, 1);
            if (gh == 0) { S->sWsB[0][p] = acc0; S->sWsB[1][p] = acc1; }
        } else if (tid >= 352) {
            const int p = tid - 352;
            const int j = p >> 4;
            float ab0, ab1;
            if (it == 0) {
                float sb = 0.f;
                #pragma unroll
                for (int gg = 0; gg < 8; gg++) {
                    sb += bias[(gg * 4 + 0) * 160 + p] + bias[(gg * 4 + 1) * 160 + p]
                        + bias[(gg * 4 + 2) * 160 + p] + bias[(gg * 4 + 3) * 160 + p];
                }
                ab0 = ab1 = 3.6f * sb;
            } else {
                const float4* cs0 = reinterpret_cast<const float4*>(S->csum[0] + j * 32);
                const float4* cs1 = reinterpret_cast<const float4*>(S->csum[1] + j * 32);
                ab0 = 0.f; ab1 = 0.f;
                #pragma unroll
                for (int gg = 0; gg < 8; gg++) {
                    float4 c40 = cs0[gg], c41 = cs1[gg];
                    float bv0 = bias[(gg * 4 + 0) * 160 + p];
                    float bv1 = bias[(gg * 4 + 1) * 160 + p];
                    float bv2 = bias[(gg * 4 + 2) * 160 + p];
                    float bv3 = bias[(gg * 4 + 3) * 160 + p];
                    ab0 += bv0 * c40.x + bv1 * c40.y + bv2 * c40.z + bv3 * c40.w;
                    ab1 += bv0 * c41.x + bv1 * c41.y + bv2 * c41.z + bv3 * c41.w;
                }
            }
            S->sWsB[0][160 + p] = ab0;
            S->sWsB[1][160 + p] = ab1;
        }
        __syncthreads();

        // ===== Phase D: squash + telescoped vsum accumulate =====
        {
            int e = -1, p = 0;
            if (tid < 160) { e = 0; p = tid; }
            else if (tid >= 256 && tid < 416) { e = 1; p = tid - 256; }
            if (e >= 0) {
                float sv = S->sWsB[e][p] + S->sWsB[e][160 + p];
                float n2 = sv * sv;
                n2 += __shfl_xor_sync(0xffffffffu, n2, 1);
                n2 += __shfl_xor_sync(0xffffffffu, n2, 2);
                n2 += __shfl_xor_sync(0xffffffffu, n2, 4);
                n2 += __shfl_xor_sync(0xffffffffu, n2, 8);
                float f  = __fdividef(sqrtf(n2), 1.0f + n2);
                float vv = sv * f;
                if (it == 2) {
                    if (e == 0 || two) out[(size_t)(e ? b1 : b0) * 160 + p] = vv;
                } else {
                    S->vsum[e][p] = (it == 0) ? LOG2E * vv : S->vsum[e][p] + LOG2E * vv;
                }
            }
        }
        if (it < 2) __syncthreads();
    }
}

extern "C" void kernel_launch(void* const* d_in, const int* in_sizes, int n_in,
                              void* d_out, int out_size) {
    const float* x    = (const float*)d_in[0];
    const float* W    = (const float*)d_in[2];
    const float* bias = (const float*)d_in[3];
    float* out = (float*)d_out;

    prep_W_kernel<<<160, 256>>>(W);

    cudaFuncSetAttribute(caps_kernel,
                         cudaFuncAttributeMaxDynamicSharedMemorySize,
                         (int)sizeof(Smem));
    caps_kernel<<<296, 512, sizeof(Smem)>>>(x, W, bias, out);
}

// round 16
// speedup vs baseline: 1.0717x; 1.0717x over previous
#include <cuda_runtime.h>
#include <cuda_fp16.h>

// CapLayer fused capsule routing. 296 CTAs x 512 threads, 2 CTAs/SM,
// 2 batch elems/CTA. fp16 streams: x (smem), W/WT (global), cx (smem).
// fp32 accumulation. Phase B quad-split with distributed csum ownership.
// Telescoped routing logits (no Phase E).
// x:    d_in[0]  float [512][256][6][6]   (channel = g*8+k, g<32, k<8)
// W:    d_in[2]  float [5120][8] ; flat = g*1280 + p*8 + k   (p = j*16+d)
// bias: d_in[3]  float [5120]    ; flat = g*160  + j*16 + d
// out:  float [512][10][16]

#define LOG2E 1.4426950408889634f

__device__ __half g_hW[40960];    // [g][p][k]
__device__ __half g_hWT[40960];   // [g][j][k][d]  (d contiguous)

struct Smem {
    __half xh[2][256 * 40];  // 40960 B, [e][gk][hw] rows padded to 40 halves
    float cbuf[16][400];     // 25600 B, per-warp c [w][j*40+hw]
    float scr[16][384];      // 24576 B, per-warp per-group per-elem vW/vb
                             //   layout: gi*192 + e*96 + {vW[j*8+k] | 80+vb[j]}
    __half cxh[2][2560];     // 10240 B, [e][j][g][k] fp16
    float csum[2][320];      // 2560 B
    float sWsB[2][320];      // 2560 B (xsum aliases [0..255] at init)
    float vsum[2][160];      // 1280 B
};                           // 107776 B (2 CTAs/SM: 215552 <= ~227KB)

__device__ __forceinline__ float ex2_approx(float x) {
    float y; asm("ex2.approx.ftz.f32 %0, %1;" : "=f"(y) : "f"(x)); return y;
}
__device__ __forceinline__ float rcp_approx(float x) {
    float y; asm("rcp.approx.ftz.f32 %0, %1;" : "=f"(y) : "f"(x)); return y;
}
__device__ __forceinline__ float dot4(float4 a, float4 b) {
    return a.x * b.x + a.y * b.y + a.z * b.z + a.w * b.w;
}
__device__ __forceinline__ float sum4(float4 a) {
    return a.x + a.y + a.z + a.w;
}
__device__ __forceinline__ void h8_to_f(uint4 h, float4& lo, float4& hi) {
    const __half2* hp = reinterpret_cast<const __half2*>(&h);
    float2 f0 = __half22float2(hp[0]);
    float2 f1 = __half22float2(hp[1]);
    float2 f2 = __half22float2(hp[2]);
    float2 f3 = __half22float2(hp[3]);
    lo = make_float4(f0.x, f0.y, f1.x, f1.y);
    hi = make_float4(f2.x, f2.y, f3.x, f3.y);
}
__device__ __forceinline__ float4 h4_to_f(uint2 u) {
    const __half2* hp = reinterpret_cast<const __half2*>(&u);
    float2 f0 = __half22float2(hp[0]);
    float2 f1 = __half22float2(hp[1]);
    return make_float4(f0.x, f0.y, f1.x, f1.y);
}

__global__ void prep_W_kernel(const float* __restrict__ W) {
    int i = blockIdx.x * 256 + threadIdx.x;
    if (i < 40960) {
        float v = W[i];                 // i = g*1280 + j*128 + d*8 + k
        g_hW[i] = __float2half(v);
        int k = i & 7, d = (i >> 3) & 15;
        int gj128 = i & ~127;
        g_hWT[gj128 + k * 16 + d] = __float2half(v);
    }
}

__global__ __launch_bounds__(512, 2)
void caps_kernel(const float* __restrict__ x_g,
                 const float* __restrict__ W,
                 const float* __restrict__ bias,
                 float* __restrict__ out) {
    extern __shared__ float smem_raw[];
    Smem* S = reinterpret_cast<Smem*>(smem_raw);

    const int cta  = blockIdx.x;
    const bool two = (cta < 216);
    const int b0   = two ? cta * 2 : 432 + (cta - 216);
    const int b1   = two ? b0 + 1 : b0;
    const int tid  = threadIdx.x;
    const int w    = tid >> 5;
    const int lane = tid & 31;

    const float* x0g = x_g + (size_t)b0 * 9216;
    const float* x1g = x_g + (size_t)b1 * 9216;

    // ---- load x, convert fp16, store padded rows ----
    for (int i = tid; i < 2304; i += 512) {
        int row  = i / 9;
        int col  = (i - row * 9) * 4;
        int dsth = row * 40 + col;
        float4 v0 = reinterpret_cast<const float4*>(x0g)[i];
        float4 v1 = reinterpret_cast<const float4*>(x1g)[i];
        __half2 a0 = __floats2half2_rn(v0.x, v0.y);
        __half2 c0 = __floats2half2_rn(v0.z, v0.w);
        __half2 a1 = __floats2half2_rn(v1.x, v1.y);
        __half2 c1 = __floats2half2_rn(v1.z, v1.w);
        uint2 u0, u1;
        u0.x = *reinterpret_cast<unsigned*>(&a0);
        u0.y = *reinterpret_cast<unsigned*>(&c0);
        u1.x = *reinterpret_cast<unsigned*>(&a1);
        u1.y = *reinterpret_cast<unsigned*>(&c1);
        *reinterpret_cast<uint2*>(&S->xh[0][dsth]) = u0;
        *reinterpret_cast<uint2*>(&S->xh[1][dsth]) = u1;
    }
    __syncthreads();

    // ---- xsum[e][g][k] = sum_hw x ----
    {
        const int e = tid >> 8, idx = tid & 255;
        const __half2* p = reinterpret_cast<const __half2*>(S->xh[e] + idx * 40);
        float acc = 0.f;
        #pragma unroll
        for (int t = 0; t < 18; t++) {
            float2 f = __half22float2(p[t]);
            acc += f.x + f.y;
        }
        S->sWsB[e][idx] = acc;
    }
    __syncthreads();

    // iter 1 shortcut: cx = 0.1*xsum (all j), stored fp16
    for (int i = tid; i < 5120; i += 512) {
        const int e = (i >= 2560);
        const int ii = i - e * 2560;
        (&S->cxh[0][0])[i] = __float2half(0.1f * S->sWsB[e][ii & 255]);
    }
    __syncthreads();

    for (int it = 0; it < 3; ++it) {
        if (it > 0) {
            float* scr = S->scr[w];

            // ===== A-pre (both groups, shared vsum loads) =====
            {
                const __half* hWT0 = g_hWT + w * 1280;
                const __half* hWT1 = g_hWT + (w + 16) * 1280;
                const float4* vs0 = reinterpret_cast<const float4*>(S->vsum[0]);
                const float4* vs1 = reinterpret_cast<const float4*>(S->vsum[1]);
                const int jj = lane >> 4;
                const int kk = (lane & 15) >> 1;
                const int dh = lane & 1;
                #pragma unroll
                for (int r = 0; r < 5; r++) {
                    const int j = 2 * r + jj;
                    float4 va0 = vs0[j * 4 + dh * 2], vc0 = vs0[j * 4 + dh * 2 + 1];
                    float4 va1 = vs1[j * 4 + dh * 2], vc1 = vs1[j * 4 + dh * 2 + 1];
                    #pragma unroll
                    for (int gi = 0; gi < 2; gi++) {
                        uint4 h = *reinterpret_cast<const uint4*>(
                            (gi ? hWT1 : hWT0) + j * 128 + kk * 16 + dh * 8);
                        float4 lo, hi;
                        h8_to_f(h, lo, hi);
                        float p0 = dot4(lo, va0) + dot4(hi, vc0);
                        float p1 = dot4(lo, va1) + dot4(hi, vc1);
                        p0 += __shfl_xor_sync(0xffffffffu, p0, 1);
                        p1 += __shfl_xor_sync(0xffffffffu, p1, 1);
                        if (dh == 0) {
                            scr[gi * 192 + j * 8 + kk]      = p0;
                            scr[gi * 192 + 96 + j * 8 + kk] = p1;
                        }
                    }
                }
                // vb for both groups (vsum loads hoisted)
                const float4* Bv = reinterpret_cast<const float4*>(bias);
                float4 vl0 = vs0[lane];
                float4 vl1 = vs1[lane];
                float4 vh0 = vs0[32 + (lane & 7)];
                float4 vh1 = vs1[32 + (lane & 7)];
                #pragma unroll
                for (int gi = 0; gi < 2; gi++) {
                    const int g = w + gi * 16;
                    float4 fa = Bv[g * 40 + lane];
                    float4 fb = Bv[g * 40 + 32 + (lane & 7)];
                    float pa0 = dot4(fa, vl0);
                    float pa1 = dot4(fa, vl1);
                    float pb0 = dot4(fb, vh0);
                    float pb1 = dot4(fb, vh1);
                    pa0 += __shfl_xor_sync(0xffffffffu, pa0, 1);
                    pa0 += __shfl_xor_sync(0xffffffffu, pa0, 2);
                    pa1 += __shfl_xor_sync(0xffffffffu, pa1, 1);
                    pa1 += __shfl_xor_sync(0xffffffffu, pa1, 2);
                    pb0 += __shfl_xor_sync(0xffffffffu, pb0, 1);
                    pb0 += __shfl_xor_sync(0xffffffffu, pb0, 2);
                    pb1 += __shfl_xor_sync(0xffffffffu, pb1, 1);
                    pb1 += __shfl_xor_sync(0xffffffffu, pb1, 2);
                    if ((lane & 3) == 0) {
                        scr[gi * 192 + 80 + (lane >> 2)]      = pa0;
                        scr[gi * 192 + 96 + 80 + (lane >> 2)] = pa1;
                        if (lane < 8) {
                            scr[gi * 192 + 88 + (lane >> 2)]      = pb0;
                            scr[gi * 192 + 96 + 88 + (lane >> 2)] = pb1;
                        }
                    }
                }
            }
            __syncwarp();

            // ===== Phase A+B per (group, element) =====
            #pragma unroll
            for (int gi = 0; gi < 2; gi++) {
                const int g = w + gi * 16;
                #pragma unroll
                for (int e = 0; e < 2; e++) {
                    const float* se = scr + gi * 192 + e * 96;
                    const __half* xge = S->xh[e];
                    // Phase A: logits -> softmax over j -> c
                    {
                        const __half* xr = xge + g * 320;
                        float xv[8], xv2[8];
                        #pragma unroll
                        for (int k = 0; k < 8; k++) {
                            xv[k]  = __half2float(xr[k * 40 + lane]);
                            xv2[k] = __half2float(xr[k * 40 + 32 + (lane & 3)]);
                        }
                        float bb[10], bb2[10];
                        #pragma unroll
                        for (int j = 0; j < 10; j++) {
                            const float4* vwp = reinterpret_cast<const float4*>(se + j * 8);
                            float4 w0 = vwp[0], w1 = vwp[1];
                            float t0 = se[80 + j];
                            float a  = t0, a2 = t0;
                            a  += w0.x*xv[0] + w0.y*xv[1] + w0.z*xv[2] + w0.w*xv[3]
                                + w1.x*xv[4] + w1.y*xv[5] + w1.z*xv[6] + w1.w*xv[7];
                            a2 += w0.x*xv2[0] + w0.y*xv2[1] + w0.z*xv2[2] + w0.w*xv2[3]
                                + w1.x*xv2[4] + w1.y*xv2[5] + w1.z*xv2[6] + w1.w*xv2[7];
                            bb[j] = a; bb2[j] = a2;
                        }
                        float Z = 0.f, Z2 = 0.f;
                        #pragma unroll
                        for (int j = 0; j < 10; j++) {
                            bb[j]  = ex2_approx(bb[j]);   Z  += bb[j];
                            bb2[j] = ex2_approx(bb2[j]);  Z2 += bb2[j];
                        }
                        float r  = rcp_approx(Z);
                        float r2 = rcp_approx(Z2);
                        float* cw = S->cbuf[w];
                        #pragma unroll
                        for (int j = 0; j < 10; j++) {
                            cw[j * 40 + lane] = bb[j] * r;
                            if (lane < 4) cw[j * 40 + 32 + lane] = bb2[j] * r2;
                        }
                    }
                    __syncwarp();
                    // Phase B: quad-split cx + distributed csum ownership
                    {
                        const int k = lane >> 2, q = lane & 3;
                        const __half* xr = xge + (g * 8 + k) * 40;
                        float4 x0 = h4_to_f(*reinterpret_cast<const uint2*>(xr + 4 * q));
                        float4 x1 = h4_to_f(*reinterpret_cast<const uint2*>(xr + 16 + 4 * q));
                        float  x2 = __half2float(xr[32 + q]);
                        const float* cb = S->cbuf[w];
                        float acc[10];
                        #pragma unroll
                        for (int j = 0; j < 10; j++) {
                            float4 c0 = *reinterpret_cast<const float4*>(cb + j * 40 + 4 * q);
                            float4 c1 = *reinterpret_cast<const float4*>(cb + j * 40 + 16 + 4 * q);
                            float  c2 = cb[j * 40 + 32 + q];
                            acc[j] = dot4(c0, x0) + dot4(c1, x1) + c2 * x2;
                        }
                        #pragma unroll
                        for (int j = 0; j < 10; j++) {
                            acc[j] += __shfl_xor_sync(0xffffffffu, acc[j], 1);
                            acc[j] += __shfl_xor_sync(0xffffffffu, acc[j], 2);
                        }
                        if (q == 0) {
                            #pragma unroll
                            for (int j = 0; j < 10; j++)
                                S->cxh[e][j * 256 + g * 8 + k] = __float2half(acc[j]);
                        }
                        // csum: k-group kk owns j=kk; kk<2 also own j=8+kk
                        {
                            const float* cro = cb + k * 40;
                            float4 c0 = *reinterpret_cast<const float4*>(cro + 4 * q);
                            float4 c1 = *reinterpret_cast<const float4*>(cro + 16 + 4 * q);
                            float cs = sum4(c0) + sum4(c1) + cro[32 + q];
                            cs += __shfl_xor_sync(0xffffffffu, cs, 1);
                            cs += __shfl_xor_sync(0xffffffffu, cs, 2);
                            if (q == 0) S->csum[e][k * 32 + g] = cs;
                            if (k < 2) {   // lanes 0..7
                                const int j2 = 8 + k;
                                const float* cr2 = cb + j2 * 40;
                                float4 d0 = *reinterpret_cast<const float4*>(cr2 + 4 * q);
                                float4 d1 = *reinterpret_cast<const float4*>(cr2 + 16 + 4 * q);
                                float cs2 = sum4(d0) + sum4(d1) + cr2[32 + q];
                                cs2 += __shfl_xor_sync(0x000000FFu, cs2, 1);
                                cs2 += __shfl_xor_sync(0x000000FFu, cs2, 2);
                                if (q == 0) S->csum[e][j2 * 32 + g] = cs2;
                            }
                        }
                    }
                    __syncwarp();
                }
            }
            __syncthreads();
        }

        // ===== Phase C: fp16 W and fp16 cx; both elements =====
        if (tid < 320) {
            const int p  = tid >> 1;
            const int gh = tid & 1;
            const int j  = p >> 4;
            const __half* cx0 = S->cxh[0];
            const __half* cx1 = S->cxh[1];
            float acc0 = 0.f, acc1 = 0.f;
            #pragma unroll 8
            for (int gg = 0; gg < 16; gg++) {
                const int g = gg * 2 + gh;
                uint4 hw_ = *reinterpret_cast<const uint4*>(&g_hW[g * 1280 + p * 8]);
                float4 wlo, whi;
                h8_to_f(hw_, wlo, whi);
                uint4 h0 = *reinterpret_cast<const uint4*>(&cx0[j * 256 + g * 8]);
                uint4 h1 = *reinterpret_cast<const uint4*>(&cx1[j * 256 + g * 8]);
                float4 a_lo, a_hi, b_lo, b_hi;
                h8_to_f(h0, a_lo, a_hi);
                h8_to_f(h1, b_lo, b_hi);
                acc0 += dot4(wlo, a_lo) + dot4(whi, a_hi);
                acc1 += dot4(wlo, b_lo) + dot4(whi, b_hi);
            }
            acc0 += __shfl_xor_sync(0xffffffffu, acc0, 1);
            acc1 += __shfl_xor_sync(0xffffffffu, acc1, 1);
            if (gh == 0) { S->sWsB[0][p] = acc0; S->sWsB[1][p] = acc1; }
        } else if (tid >= 352) {
            const int p = tid - 352;
            const int j = p >> 4;
            float ab0, ab1;
            if (it == 0) {
                float sb = 0.f;
                #pragma unroll
                for (int gg = 0; gg < 8; gg++) {
                    sb += bias[(gg * 4 + 0) * 160 + p] + bias[(gg * 4 + 1) * 160 + p]
                        + bias[(gg * 4 + 2) * 160 + p] + bias[(gg * 4 + 3) * 160 + p];
                }
                ab0 = ab1 = 3.6f * sb;
            } else {
                const float4* cs0 = reinterpret_cast<const float4*>(S->csum[0] + j * 32);
                const float4* cs1 = reinterpret_cast<const float4*>(S->csum[1] + j * 32);
                ab0 = 0.f; ab1 = 0.f;
                #pragma unroll
                for (int gg = 0; gg < 8; gg++) {
                    float4 c40 = cs0[gg], c41 = cs1[gg];
                    float bv0 = bias[(gg * 4 + 0) * 160 + p];
                    float bv1 = bias[(gg * 4 + 1) * 160 + p];
                    float bv2 = bias[(gg * 4 + 2) * 160 + p];
                    float bv3 = bias[(gg * 4 + 3) * 160 + p];
                    ab0 += bv0 * c40.x + bv1 * c40.y + bv2 * c40.z + bv3 * c40.w;
                    ab1 += bv0 * c41.x + bv1 * c41.y + bv2 * c41.z + bv3 * c41.w;
                }
            }
            S->sWsB[0][160 + p] = ab0;
            S->sWsB[1][160 + p] = ab1;
        }
        __syncthreads();

        // ===== Phase D: squash + telescoped vsum accumulate =====
        {
            int e = -1, p = 0;
            if (tid < 160) { e = 0; p = tid; }
            else if (tid >= 256 && tid < 416) { e = 1; p = tid - 256; }
            if (e >= 0) {
                float sv = S->sWsB[e][p] + S->sWsB[e][160 + p];
                float n2 = sv * sv;
                n2 += __shfl_xor_sync(0xffffffffu, n2, 1);
                n2 += __shfl_xor_sync(0xffffffffu, n2, 2);
                n2 += __shfl_xor_sync(0xffffffffu, n2, 4);
                n2 += __shfl_xor_sync(0xffffffffu, n2, 8);
                float f  = __fdividef(sqrtf(n2), 1.0f + n2);
                float vv = sv * f;
                if (it == 2) {
                    if (e == 0 || two) out[(size_t)(e ? b1 : b0) * 160 + p] = vv;
                } else {
                    S->vsum[e][p] = (it == 0) ? LOG2E * vv : S->vsum[e][p] + LOG2E * vv;
                }
            }
        }
        if (it < 2) __syncthreads();
    }
}

extern "C" void kernel_launch(void* const* d_in, const int* in_sizes, int n_in,
                              void* d_out, int out_size) {
    const float* x    = (const float*)d_in[0];
    const float* W    = (const float*)d_in[2];
    const float* bias = (const float*)d_in[3];
    float* out = (float*)d_out;

    prep_W_kernel<<<160, 256>>>(W);

    cudaFuncSetAttribute(caps_kernel,
                         cudaFuncAttributeMaxDynamicSharedMemorySize,
                         (int)sizeof(Smem));
    caps_kernel<<<296, 512, sizeof(Smem)>>>(x, W, bias, out);
}

// round 17
// speedup vs baseline: 1.1835x; 1.1044x over previous
#include <cuda_runtime.h>
#include <cuda_fp16.h>

// CapLayer fused capsule routing. 296 CTAs x 512 threads, 2 CTAs/SM,
// 2 batch elems/CTA. fp16 streams: x (smem), c (smem), cx (smem), W/WT
// (global). fp32 accumulation. Telescoped routing logits (no Phase E).
// x:    d_in[0]  float [512][256][6][6]   (channel = g*8+k, g<32, k<8)
// W:    d_in[2]  float [5120][8] ; flat = g*1280 + p*8 + k   (p = j*16+d)
// bias: d_in[3]  float [5120]    ; flat = g*160  + j*16 + d
// out:  float [512][10][16]

#define LOG2E 1.4426950408889634f

__device__ __half g_hW[40960];    // [g][p][k]
__device__ __half g_hWT[40960];   // [g][j][k][d]  (d contiguous)

struct Smem {
    __half xh[2][256 * 40];  // 40960 B, [e][gk][hw] rows padded to 40 halves
    __half cbufh[16][400];   // 12800 B, per-warp c [w][j*40+hw] fp16
    float scr[16][384];      // 24576 B, per-warp per-group per-elem vW/vb
                             //   layout: gi*192 + e*96 + {vW[j*8+k] | 80+vb[j]}
    __half cxh[2][2560];     // 10240 B, [e][j][g][k] fp16
    float csum[2][320];      // 2560 B
    float sWsB[2][320];      // 2560 B (xsum aliases [0..255] at init)
    float vsum[2][160];      // 1280 B
};                           // 94976 B (2 CTAs/SM: 189952)

__device__ __forceinline__ float ex2_approx(float x) {
    float y; asm("ex2.approx.ftz.f32 %0, %1;" : "=f"(y) : "f"(x)); return y;
}
__device__ __forceinline__ float rcp_approx(float x) {
    float y; asm("rcp.approx.ftz.f32 %0, %1;" : "=f"(y) : "f"(x)); return y;
}
__device__ __forceinline__ float dot4(float4 a, float4 b) {
    return a.x * b.x + a.y * b.y + a.z * b.z + a.w * b.w;
}
__device__ __forceinline__ float sum4(float4 a) {
    return a.x + a.y + a.z + a.w;
}
__device__ __forceinline__ void h8_to_f(uint4 h, float4& lo, float4& hi) {
    const __half2* hp = reinterpret_cast<const __half2*>(&h);
    float2 f0 = __half22float2(hp[0]);
    float2 f1 = __half22float2(hp[1]);
    float2 f2 = __half22float2(hp[2]);
    float2 f3 = __half22float2(hp[3]);
    lo = make_float4(f0.x, f0.y, f1.x, f1.y);
    hi = make_float4(f2.x, f2.y, f3.x, f3.y);
}
__device__ __forceinline__ float4 h4_to_f(uint2 u) {
    const __half2* hp = reinterpret_cast<const __half2*>(&u);
    float2 f0 = __half22float2(hp[0]);
    float2 f1 = __half22float2(hp[1]);
    return make_float4(f0.x, f0.y, f1.x, f1.y);
}

__global__ void prep_W_kernel(const float* __restrict__ W) {
    int i = blockIdx.x * 256 + threadIdx.x;
    if (i < 40960) {
        float v = W[i];                 // i = g*1280 + j*128 + d*8 + k
        g_hW[i] = __float2half(v);
        int k = i & 7, d = (i >> 3) & 15;
        int gj128 = i & ~127;
        g_hWT[gj128 + k * 16 + d] = __float2half(v);
    }
}

__global__ __launch_bounds__(512, 2)
void caps_kernel(const float* __restrict__ x_g,
                 const float* __restrict__ W,
                 const float* __restrict__ bias,
                 float* __restrict__ out) {
    extern __shared__ float smem_raw[];
    Smem* S = reinterpret_cast<Smem*>(smem_raw);

    const int cta  = blockIdx.x;
    const bool two = (cta < 216);
    const int b0   = two ? cta * 2 : 432 + (cta - 216);
    const int b1   = two ? b0 + 1 : b0;
    const int tid  = threadIdx.x;
    const int w    = tid >> 5;
    const int lane = tid & 31;

    const float* x0g = x_g + (size_t)b0 * 9216;
    const float* x1g = x_g + (size_t)b1 * 9216;

    // ---- load x, convert fp16, store padded rows ----
    for (int i = tid; i < 2304; i += 512) {
        int row  = i / 9;
        int col  = (i - row * 9) * 4;
        int dsth = row * 40 + col;
        float4 v0 = reinterpret_cast<const float4*>(x0g)[i];
        float4 v1 = reinterpret_cast<const float4*>(x1g)[i];
        __half2 a0 = __floats2half2_rn(v0.x, v0.y);
        __half2 c0 = __floats2half2_rn(v0.z, v0.w);
        __half2 a1 = __floats2half2_rn(v1.x, v1.y);
        __half2 c1 = __floats2half2_rn(v1.z, v1.w);
        uint2 u0, u1;
        u0.x = *reinterpret_cast<unsigned*>(&a0);
        u0.y = *reinterpret_cast<unsigned*>(&c0);
        u1.x = *reinterpret_cast<unsigned*>(&a1);
        u1.y = *reinterpret_cast<unsigned*>(&c1);
        *reinterpret_cast<uint2*>(&S->xh[0][dsth]) = u0;
        *reinterpret_cast<uint2*>(&S->xh[1][dsth]) = u1;
    }
    __syncthreads();

    // ---- xsum[e][g][k] = sum_hw x ----
    {
        const int e = tid >> 8, idx = tid & 255;
        const __half2* p = reinterpret_cast<const __half2*>(S->xh[e] + idx * 40);
        float acc = 0.f;
        #pragma unroll
        for (int t = 0; t < 18; t++) {
            float2 f = __half22float2(p[t]);
            acc += f.x + f.y;
        }
        S->sWsB[e][idx] = acc;
    }
    __syncthreads();

    // iter 1 shortcut: cx = 0.1*xsum (all j), stored fp16
    for (int i = tid; i < 5120; i += 512) {
        const int e = (i >= 2560);
        const int ii = i - e * 2560;
        (&S->cxh[0][0])[i] = __float2half(0.1f * S->sWsB[e][ii & 255]);
    }
    __syncthreads();

    for (int it = 0; it < 3; ++it) {
        if (it > 0) {
            float* scr = S->scr[w];

            // ===== A-pre (both groups, shared vsum loads) =====
            {
                const __half* hWT0 = g_hWT + w * 1280;
                const __half* hWT1 = g_hWT + (w + 16) * 1280;
                const float4* vs0 = reinterpret_cast<const float4*>(S->vsum[0]);
                const float4* vs1 = reinterpret_cast<const float4*>(S->vsum[1]);
                const int jj = lane >> 4;
                const int kk = (lane & 15) >> 1;
                const int dh = lane & 1;
                #pragma unroll
                for (int r = 0; r < 5; r++) {
                    const int j = 2 * r + jj;
                    float4 va0 = vs0[j * 4 + dh * 2], vc0 = vs0[j * 4 + dh * 2 + 1];
                    float4 va1 = vs1[j * 4 + dh * 2], vc1 = vs1[j * 4 + dh * 2 + 1];
                    #pragma unroll
                    for (int gi = 0; gi < 2; gi++) {
                        uint4 h = *reinterpret_cast<const uint4*>(
                            (gi ? hWT1 : hWT0) + j * 128 + kk * 16 + dh * 8);
                        float4 lo, hi;
                        h8_to_f(h, lo, hi);
                        float p0 = dot4(lo, va0) + dot4(hi, vc0);
                        float p1 = dot4(lo, va1) + dot4(hi, vc1);
                        p0 += __shfl_xor_sync(0xffffffffu, p0, 1);
                        p1 += __shfl_xor_sync(0xffffffffu, p1, 1);
                        if (dh == 0) {
                            scr[gi * 192 + j * 8 + kk]      = p0;
                            scr[gi * 192 + 96 + j * 8 + kk] = p1;
                        }
                    }
                }
                // vb for both groups (vsum loads hoisted)
                const float4* Bv = reinterpret_cast<const float4*>(bias);
                float4 vl0 = vs0[lane];
                float4 vl1 = vs1[lane];
                float4 vh0 = vs0[32 + (lane & 7)];
                float4 vh1 = vs1[32 + (lane & 7)];
                #pragma unroll
                for (int gi = 0; gi < 2; gi++) {
                    const int g = w + gi * 16;
                    float4 fa = Bv[g * 40 + lane];
                    float4 fb = Bv[g * 40 + 32 + (lane & 7)];
                    float pa0 = dot4(fa, vl0);
                    float pa1 = dot4(fa, vl1);
                    float pb0 = dot4(fb, vh0);
                    float pb1 = dot4(fb, vh1);
                    pa0 += __shfl_xor_sync(0xffffffffu, pa0, 1);
                    pa0 += __shfl_xor_sync(0xffffffffu, pa0, 2);
                    pa1 += __shfl_xor_sync(0xffffffffu, pa1, 1);
                    pa1 += __shfl_xor_sync(0xffffffffu, pa1, 2);
                    pb0 += __shfl_xor_sync(0xffffffffu, pb0, 1);
                    pb0 += __shfl_xor_sync(0xffffffffu, pb0, 2);
                    pb1 += __shfl_xor_sync(0xffffffffu, pb1, 1);
                    pb1 += __shfl_xor_sync(0xffffffffu, pb1, 2);
                    if ((lane & 3) == 0) {
                        scr[gi * 192 + 80 + (lane >> 2)]      = pa0;
                        scr[gi * 192 + 96 + 80 + (lane >> 2)] = pa1;
                        if (lane < 8) {
                            scr[gi * 192 + 88 + (lane >> 2)]      = pb0;
                            scr[gi * 192 + 96 + 88 + (lane >> 2)] = pb1;
                        }
                    }
                }
            }
            __syncwarp();

            // ===== Phase A+B per (group, element) =====
            #pragma unroll
            for (int gi = 0; gi < 2; gi++) {
                const int g = w + gi * 16;
                #pragma unroll
                for (int e = 0; e < 2; e++) {
                    const float* se = scr + gi * 192 + e * 96;
                    const __half* xge = S->xh[e];
                    // Phase A: logits -> softmax over j -> c (fp16 store)
                    {
                        const __half* xr = xge + g * 320;
                        float xv[8], xv2[8];
                        #pragma unroll
                        for (int k = 0; k < 8; k++) {
                            xv[k]  = __half2float(xr[k * 40 + lane]);
                            xv2[k] = __half2float(xr[k * 40 + 32 + (lane & 3)]);
                        }
                        // hoisted vb loads (3 vector LDS)
                        float4 vb03 = *reinterpret_cast<const float4*>(se + 80);
                        float4 vb47 = *reinterpret_cast<const float4*>(se + 84);
                        float2 vb89 = *reinterpret_cast<const float2*>(se + 88);
                        const float vbs[10] = {vb03.x, vb03.y, vb03.z, vb03.w,
                                               vb47.x, vb47.y, vb47.z, vb47.w,
                                               vb89.x, vb89.y};
                        float bb[10], bb2[10];
                        #pragma unroll
                        for (int j = 0; j < 10; j++) {
                            const float4* vwp = reinterpret_cast<const float4*>(se + j * 8);
                            float4 w0 = vwp[0], w1 = vwp[1];
                            float t0 = vbs[j];
                            float a  = t0, a2 = t0;
                            a  += w0.x*xv[0] + w0.y*xv[1] + w0.z*xv[2] + w0.w*xv[3]
                                + w1.x*xv[4] + w1.y*xv[5] + w1.z*xv[6] + w1.w*xv[7];
                            a2 += w0.x*xv2[0] + w0.y*xv2[1] + w0.z*xv2[2] + w0.w*xv2[3]
                                + w1.x*xv2[4] + w1.y*xv2[5] + w1.z*xv2[6] + w1.w*xv2[7];
                            bb[j] = a; bb2[j] = a2;
                        }
                        float Z = 0.f, Z2 = 0.f;
                        #pragma unroll
                        for (int j = 0; j < 10; j++) {
                            bb[j]  = ex2_approx(bb[j]);   Z  += bb[j];
                            bb2[j] = ex2_approx(bb2[j]);  Z2 += bb2[j];
                        }
                        float r  = rcp_approx(Z);
                        float r2 = rcp_approx(Z2);
                        __half* cw = S->cbufh[w];
                        #pragma unroll
                        for (int j = 0; j < 10; j++) {
                            cw[j * 40 + lane] = __float2half(bb[j] * r);
                            if (lane < 4) cw[j * 40 + 32 + lane] = __float2half(bb2[j] * r2);
                        }
                    }
                    __syncwarp();
                    // Phase B: quad-split cx + distributed csum, fp16 c reads
                    {
                        const int k = lane >> 2, q = lane & 3;
                        const __half* xr = xge + (g * 8 + k) * 40;
                        float4 x0 = h4_to_f(*reinterpret_cast<const uint2*>(xr + 4 * q));
                        float4 x1 = h4_to_f(*reinterpret_cast<const uint2*>(xr + 16 + 4 * q));
                        float  x2 = __half2float(xr[32 + q]);
                        const __half* cb = S->cbufh[w];
                        float acc[10];
                        #pragma unroll
                        for (int j = 0; j < 10; j++) {
                            float4 c0 = h4_to_f(*reinterpret_cast<const uint2*>(cb + j * 40 + 4 * q));
                            float4 c1 = h4_to_f(*reinterpret_cast<const uint2*>(cb + j * 40 + 16 + 4 * q));
                            float  c2 = __half2float(cb[j * 40 + 32 + q]);
                            acc[j] = dot4(c0, x0) + dot4(c1, x1) + c2 * x2;
                        }
                        #pragma unroll
                        for (int j = 0; j < 10; j++) {
                            acc[j] += __shfl_xor_sync(0xffffffffu, acc[j], 1);
                            acc[j] += __shfl_xor_sync(0xffffffffu, acc[j], 2);
                        }
                        if (q == 0) {
                            #pragma unroll
                            for (int j = 0; j < 10; j++)
                                S->cxh[e][j * 256 + g * 8 + k] = __float2half(acc[j]);
                        }
                        // csum: k-group kk owns j=kk; kk<2 also own j=8+kk
                        {
                            const __half* cro = cb + k * 40;
                            float4 c0 = h4_to_f(*reinterpret_cast<const uint2*>(cro + 4 * q));
                            float4 c1 = h4_to_f(*reinterpret_cast<const uint2*>(cro + 16 + 4 * q));
                            float cs = sum4(c0) + sum4(c1) + __half2float(cro[32 + q]);
                            cs += __shfl_xor_sync(0xffffffffu, cs, 1);
                            cs += __shfl_xor_sync(0xffffffffu, cs, 2);
                            if (q == 0) S->csum[e][k * 32 + g] = cs;
                            if (k < 2) {
                                const int j2 = 8 + k;
                                const __half* cr2 = cb + j2 * 40;
                                float4 d0 = h4_to_f(*reinterpret_cast<const uint2*>(cr2 + 4 * q));
                                float4 d1 = h4_to_f(*reinterpret_cast<const uint2*>(cr2 + 16 + 4 * q));
                                float cs2 = sum4(d0) + sum4(d1) + __half2float(cr2[32 + q]);
                                cs2 += __shfl_xor_sync(0x000000FFu, cs2, 1);
                                cs2 += __shfl_xor_sync(0x000000FFu, cs2, 2);
                                if (q == 0) S->csum[e][j2 * 32 + g] = cs2;
                            }
                        }
                    }
                    __syncwarp();
                }
            }
            __syncthreads();
        }

        // ===== Phase C: fp16 W and fp16 cx; both elements =====
        if (tid < 320) {
            const int p  = tid >> 1;
            const int gh = tid & 1;
            const int j  = p >> 4;
            const __half* cx0 = S->cxh[0];
            const __half* cx1 = S->cxh[1];
            float acc0 = 0.f, acc1 = 0.f;
            #pragma unroll 8
            for (int gg = 0; gg < 16; gg++) {
                const int g = gg * 2 + gh;
                uint4 hw_ = *reinterpret_cast<const uint4*>(&g_hW[g * 1280 + p * 8]);
                float4 wlo, whi;
                h8_to_f(hw_, wlo, whi);
                uint4 h0 = *reinterpret_cast<const uint4*>(&cx0[j * 256 + g * 8]);
                uint4 h1 = *reinterpret_cast<const uint4*>(&cx1[j * 256 + g * 8]);
                float4 a_lo, a_hi, b_lo, b_hi;
                h8_to_f(h0, a_lo, a_hi);
                h8_to_f(h1, b_lo, b_hi);
                acc0 += dot4(wlo, a_lo) + dot4(whi, a_hi);
                acc1 += dot4(wlo, b_lo) + dot4(whi, b_hi);
            }
            acc0 += __shfl_xor_sync(0xffffffffu, acc0, 1);
            acc1 += __shfl_xor_sync(0xffffffffu, acc1, 1);
            if (gh == 0) { S->sWsB[0][p] = acc0; S->sWsB[1][p] = acc1; }
        } else if (tid >= 352) {
            const int p = tid - 352;
            const int j = p >> 4;
            float ab0, ab1;
            if (it == 0) {
                float sb = 0.f;
                #pragma unroll
                for (int gg = 0; gg < 8; gg++) {
                    sb += bias[(gg * 4 + 0) * 160 + p] + bias[(gg * 4 + 1) * 160 + p]
                        + bias[(gg * 4 + 2) * 160 + p] + bias[(gg * 4 + 3) * 160 + p];
                }
                ab0 = ab1 = 3.6f * sb;
            } else {
                const float4* cs0 = reinterpret_cast<const float4*>(S->csum[0] + j * 32);
                const float4* cs1 = reinterpret_cast<const float4*>(S->csum[1] + j * 32);
                ab0 = 0.f; ab1 = 0.f;
                #pragma unroll
                for (int gg = 0; gg < 8; gg++) {
                    float4 c40 = cs0[gg], c41 = cs1[gg];
                    float bv0 = bias[(gg * 4 + 0) * 160 + p];
                    float bv1 = bias[(gg * 4 + 1) * 160 + p];
                    float bv2 = bias[(gg * 4 + 2) * 160 + p];
                    float bv3 = bias[(gg * 4 + 3) * 160 + p];
                    ab0 += bv0 * c40.x + bv1 * c40.y + bv2 * c40.z + bv3 * c40.w;
                    ab1 += bv0 * c41.x + bv1 * c41.y + bv2 * c41.z + bv3 * c41.w;
                }
            }
            S->sWsB[0][160 + p] = ab0;
            S->sWsB[1][160 + p] = ab1;
        }
        __syncthreads();

        // ===== Phase D: squash + telescoped vsum accumulate =====
        {
            int e = -1, p = 0;
            if (tid < 160) { e = 0; p = tid; }
            else if (tid >= 256 && tid < 416) { e = 1; p = tid - 256; }
            if (e >= 0) {
                float sv = S->sWsB[e][p] + S->sWsB[e][160 + p];
                float n2 = sv * sv;
                n2 += __shfl_xor_sync(0xffffffffu, n2, 1);
                n2 += __shfl_xor_sync(0xffffffffu, n2, 2);
                n2 += __shfl_xor_sync(0xffffffffu, n2, 4);
                n2 += __shfl_xor_sync(0xffffffffu, n2, 8);
                float f  = __fdividef(sqrtf(n2), 1.0f + n2);
                float vv = sv * f;
                if (it == 2) {
                    if (e == 0 || two) out[(size_t)(e ? b1 : b0) * 160 + p] = vv;
                } else {
                    S->vsum[e][p] = (it == 0) ? LOG2E * vv : S->vsum[e][p] + LOG2E * vv;
                }
            }
        }
        if (it < 2) __syncthreads();
    }
}

extern "C" void kernel_launch(void* const* d_in, const int* in_sizes, int n_in,
                              void* d_out, int out_size) {
    const float* x    = (const float*)d_in[0];
    const float* W    = (const float*)d_in[2];
    const float* bias = (const float*)d_in[3];
    float* out = (float*)d_out;

    prep_W_kernel<<<160, 256>>>(W);

    cudaFuncSetAttribute(caps_kernel,
                         cudaFuncAttributeMaxDynamicSharedMemorySize,
                         (int)sizeof(Smem));
    caps_kernel<<<296, 512, sizeof(Smem)>>>(x, W, bias, out);
}